// round 1
// baseline (speedup 1.0000x reference)
#include <cuda_runtime.h>
#include <math.h>

// N x N mask, N = t*h*w. value = 0.0f if (local window ||_inf <= 2) OR
// (diff along exactly one axis in {1,2,4}, other axes equal), else -FLT_MAX.
// Pure store-bound kernel: one float4 (4 columns) per thread, row per blockIdx.y.

__global__ void __launch_bounds__(256)
hybrid_mask_kernel(const int* __restrict__ hp, const int* __restrict__ wp,
                   float4* __restrict__ out, int N) {
    const int h = *hp;
    const int w = *wp;

    const int i  = blockIdx.y;                                   // row index
    const int j4 = blockIdx.x * blockDim.x + threadIdx.x;        // float4 col index
    const int j0 = j4 * 4;
    if (j0 >= N) return;

    // decode row coordinate (uniform across block)
    const int wi = i % w;
    const int ri = i / w;
    const int hi = ri % h;
    const int ti = ri / h;

    // decode base column coordinate
    int wj = j0 % w;
    const int rj = j0 / w;
    int hj = rj % h;
    int tj = rj / h;

    const float NEG = -3.402823466e+38f;  // -FLT_MAX == jnp.finfo(f32).min
    float vals[4];

    #pragma unroll
    for (int k = 0; k < 4; k++) {
        // advance column coord by k with carry (w >= 4 assumed; k <= 3)
        int wjk = wj + k, hjk = hj, tjk = tj;
        if (wjk >= w) { wjk -= w; hjk += 1; if (hjk >= h) { hjk = 0; tjk += 1; } }

        const int dt = abs(ti - tjk);
        const int dh = abs(hi - hjk);
        const int dw = abs(wi - wjk);

        const bool local = (dt <= 2) & (dh <= 2) & (dw <= 2);

        const bool pt = (dt == 1) | (dt == 2) | (dt == 4);
        const bool ph = (dh == 1) | (dh == 2) | (dh == 4);
        const bool pw = (dw == 1) | (dw == 2) | (dw == 4);

        const bool zt = (dt == 0), zh = (dh == 0), zw = (dw == 0);

        const bool sparse = (pt & zh & zw) | (ph & zt & zw) | (pw & zt & zh);

        vals[k] = (local | sparse) ? 0.0f : NEG;
    }

    out[(size_t)i * (size_t)(N >> 2) + (size_t)j4] =
        make_float4(vals[0], vals[1], vals[2], vals[3]);
}

extern "C" void kernel_launch(void* const* d_in, const int* in_sizes, int n_in,
                              void* d_out, int out_size) {
    // out is N*N floats -> N = sqrt(out_size)
    const int N = (int)(sqrt((double)out_size) + 0.5);

    // inputs per metadata order: t, h, w (scalars, int32). t is implied by N/(h*w).
    const int* hp = (const int*)d_in[1];
    const int* wp = (const int*)d_in[2];

    dim3 block(256);
    dim3 grid((unsigned)(((N / 4) + 255) / 256), (unsigned)N);
    hybrid_mask_kernel<<<grid, block>>>(hp, wp, (float4*)d_out, N);
}

// round 2
// speedup vs baseline: 2.9663x; 2.9663x over previous
#include <cuda_runtime.h>
#include <math.h>

#define NEG_F (-3.402823466e+38f)   // jnp.finfo(float32).min == -FLT_MAX

// ---------------------------------------------------------------------------
// Kernel 1: fill the entire N*N output with -FLT_MAX. Pure store stream.
// ---------------------------------------------------------------------------
__global__ void __launch_bounds__(256)
fill_neg_kernel(float4* __restrict__ out, size_t n4) {
    size_t idx    = (size_t)blockIdx.x * blockDim.x + threadIdx.x;
    size_t stride = (size_t)gridDim.x * blockDim.x;
    const float4 v = make_float4(NEG_F, NEG_F, NEG_F, NEG_F);
    #pragma unroll 4
    for (; idx < n4; idx += stride) out[idx] = v;
}

// ---------------------------------------------------------------------------
// Kernel 2: scatter 0.0f at the masked positions.
// For each row i (one block per row), the masked columns j are:
//   - local window: dt,dh,dw in [-2,2]  -> 125 candidates
//   - sparse power-of-two {1,2,4} along exactly one axis, other axes 0.
//     offsets 1,2 are already inside the local window; only +/-4 along each
//     axis adds new entries -> 6 candidates.
// Total 131 candidates per row; bounds-check against the grid.
// ---------------------------------------------------------------------------
__global__ void __launch_bounds__(160)
scatter_zero_kernel(const int* __restrict__ tp, const int* __restrict__ hp,
                    const int* __restrict__ wp, float* __restrict__ out, int N) {
    const int t = *tp;
    const int h = *hp;
    const int w = *wp;

    const int i = blockIdx.x;            // row index
    const int tid = threadIdx.x;
    if (tid >= 131) return;

    // decode row coordinate
    const int wi = i % w;
    const int ri = i / w;
    const int hi = ri % h;
    const int ti = ri / h;

    int dt, dh, dw;
    if (tid < 125) {
        dt = tid / 25 - 2;
        dh = (tid / 5) % 5 - 2;
        dw = tid % 5 - 2;
    } else {
        const int s = tid - 125;         // 0..5
        const int axis = s >> 1;         // 0:t 1:h 2:w
        const int off  = (s & 1) ? 4 : -4;
        dt = (axis == 0) ? off : 0;
        dh = (axis == 1) ? off : 0;
        dw = (axis == 2) ? off : 0;
    }

    const int tj = ti + dt;
    const int hj = hi + dh;
    const int wj = wi + dw;
    if ((unsigned)tj >= (unsigned)t) return;
    if ((unsigned)hj >= (unsigned)h) return;
    if ((unsigned)wj >= (unsigned)w) return;

    const int j = (tj * h + hj) * w + wj;
    out[(size_t)i * (size_t)N + (size_t)j] = 0.0f;
}

// ---------------------------------------------------------------------------
extern "C" void kernel_launch(void* const* d_in, const int* in_sizes, int n_in,
                              void* d_out, int out_size) {
    const int N = (int)(sqrt((double)out_size) + 0.5);   // out is N*N floats

    const int* tp = (const int*)d_in[0];
    const int* hp = (const int*)d_in[1];
    const int* wp = (const int*)d_in[2];

    // Fill: float4 main body (out_size for this problem is divisible by 4).
    size_t n4 = (size_t)out_size / 4;
    int fill_blocks = (int)((n4 + 256 * 4 - 1) / (256 * 4));
    if (fill_blocks > 65535) fill_blocks = 65535;
    fill_neg_kernel<<<fill_blocks, 256>>>((float4*)d_out, n4);

    // Scalar tail (defensive; no-op when out_size % 4 == 0)
    // handled by scatter ordering only over masked entries, so fill the tail
    // here with a tiny kernel if needed:
    // (out_size = N*N with N = 8192 -> divisible by 4, skip)

    // Scatter zeros, one block per row.
    scatter_zero_kernel<<<N, 160>>>(tp, hp, wp, (float*)d_out, N);
}

// round 3
// speedup vs baseline: 3.8547x; 1.2995x over previous
#include <cuda_runtime.h>
#include <math.h>

#define NEG_F (-3.402823466e+38f)   // jnp.finfo(float32).min == -FLT_MAX

// ---------------------------------------------------------------------------
// One block per row i of the N x N mask (N = t*h*w).
//   Phase 1: stream the whole row with -FLT_MAX (coalesced float4 stores).
//   Phase 2: after __syncthreads, threads 0..130 overwrite the <=131 masked
//            columns with 0.0f. These land on L2-dirty sectors written in
//            phase 1 by this same block, so they merge in L2: no extra DRAM
//            traffic, no separate scatter kernel.
// Masked columns per row:
//   - local window: dt,dh,dw in [-2,2]                      -> 125 candidates
//   - sparse pow2 {1,2,4} along exactly one axis (others 0) -> only +/-4 adds
//     new entries (1,2 are inside the window)               ->   6 candidates
// ---------------------------------------------------------------------------
__global__ void __launch_bounds__(256)
fused_mask_kernel(const int* __restrict__ tp, const int* __restrict__ hp,
                  const int* __restrict__ wp, float4* __restrict__ out4, int N) {
    const int i  = blockIdx.x;          // row index
    const int n4 = N >> 2;              // float4s per row

    // ---- Phase 1: fill row with -FLT_MAX ----
    float4* row = out4 + (size_t)i * (size_t)n4;
    const float4 v = make_float4(NEG_F, NEG_F, NEG_F, NEG_F);
    #pragma unroll 8
    for (int f = threadIdx.x; f < n4; f += 256) row[f] = v;

    __syncthreads();

    // ---- Phase 2: overwrite masked columns with 0.0f ----
    const int tid = threadIdx.x;
    if (tid < 131) {
        const int t = *tp;
        const int h = *hp;
        const int w = *wp;

        // decode row coordinate
        const int wi = i % w;
        const int ri = i / w;
        const int hi = ri % h;
        const int ti = ri / h;

        int dt, dh, dw;
        if (tid < 125) {
            dt = tid / 25 - 2;
            dh = (tid / 5) % 5 - 2;
            dw = tid % 5 - 2;
        } else {
            const int s    = tid - 125;        // 0..5
            const int axis = s >> 1;           // 0:t 1:h 2:w
            const int off  = (s & 1) ? 4 : -4;
            dt = (axis == 0) ? off : 0;
            dh = (axis == 1) ? off : 0;
            dw = (axis == 2) ? off : 0;
        }

        const int tj = ti + dt;
        const int hj = hi + dh;
        const int wj = wi + dw;
        if ((unsigned)tj < (unsigned)t &&
            (unsigned)hj < (unsigned)h &&
            (unsigned)wj < (unsigned)w) {
            const int j = (tj * h + hj) * w + wj;
            ((float*)row)[j] = 0.0f;
        }
    }
}

// ---------------------------------------------------------------------------
extern "C" void kernel_launch(void* const* d_in, const int* in_sizes, int n_in,
                              void* d_out, int out_size) {
    const int N = (int)(sqrt((double)out_size) + 0.5);   // out is N*N floats

    const int* tp = (const int*)d_in[0];
    const int* hp = (const int*)d_in[1];
    const int* wp = (const int*)d_in[2];

    fused_mask_kernel<<<N, 256>>>(tp, hp, wp, (float4*)d_out, N);
}